// round 16
// baseline (speedup 1.0000x reference)
#include <cuda_runtime.h>
#include <cuda_fp16.h>
#include <cstdint>

#define N_USER 50000
#define N_ITEM 100000
#define NTOT   150000
#define NTOTP  150016            // padded to multiple of 128 (dense block rows)
#define NNZ    3000000
#define EMB    64
#define BATCH  4096
#define NPAD   (NNZ + NTOT * 4 + 8)   // edges + worst-case per-row pad (x4)

// ---------------- device scratch (no allocation allowed) --------------------
__device__ __align__(16) __half2 g_egoA[(size_t)NTOTP * 32];  // init ego, then layer-3 ego
__device__ __align__(16) __half2 g_egoB[(size_t)NTOTP * 32];  // layer-1 ego
__device__ __align__(16) __half2 g_egoC[(size_t)NTOTP * 32];  // layer-2 ego
__device__ __align__(16) __half2 g_side16[(size_t)NTOTP * 32];// fp16 side scratch
__device__ float g_inv[3][NTOTP];                             // per-layer inv norms
__device__ __align__(16) unsigned g_edges[(size_t)NPAD * 2];  // {col, valbits} pairs
__device__ int g_cnt[NTOT];     // zeroed by k_out at end of every call
__device__ int g_start[NTOT];
__device__ int g_cur[NTOT];
__device__ int g_ctr;           // zeroed by k_out at end of every call

// ---------------------------------------------------------------------------
// launch 0: fused init + histogram. g_cnt/g_ctr zero at entry.
// ---------------------------------------------------------------------------
__global__ void k_init_hist(const float4* __restrict__ ue, const float4* __restrict__ ie,
                            const int* __restrict__ rows) {
    int i = blockIdx.x * blockDim.x + threadIdx.x;   // grid covers NNZ (3M)
    if (i < NTOT * 16) {
        float4 v = (i < N_USER * 16) ? ue[i] : ie[i - N_USER * 16];
        g_egoA[2 * i]     = __floats2half2_rn(v.x, v.y);
        g_egoA[2 * i + 1] = __floats2half2_rn(v.z, v.w);
    }
    if (i < NNZ) atomicAdd(&g_cnt[rows[i]], 1);
}

// launch 1: atomic segment allocation (x4-padded); writes {0,0} pad edges.
__global__ void k_alloc() {
    int r = blockIdx.x * blockDim.x + threadIdx.x;
    if (r >= NTOT) return;
    int cnt = g_cnt[r];
    int c4  = (cnt + 3) & ~3;
    int s = atomicAdd(&g_ctr, c4);
    g_start[r] = s;
    g_cur[r]   = s;
    uint2* ez = reinterpret_cast<uint2*>(g_edges);
    for (int j = cnt; j < c4; j++) ez[s + j] = make_uint2(0u, 0u);
}

// launch 2: permute edges into row-grouped segments
__global__ void k_fill(const int* __restrict__ rows, const int* __restrict__ cols,
                       const float* __restrict__ vals) {
    int i = blockIdx.x * blockDim.x + threadIdx.x;
    if (i >= NNZ) return;
    int r = rows[i];
    int p = atomicAdd(&g_cur[r], 1);
    uint2* ez = reinterpret_cast<uint2*>(g_edges);
    ez[p] = make_uint2((unsigned)cols[i], __float_as_uint(vals[i]));
}

// ---------------------------------------------------------------------------
// gather: LSU-minimal. One LDG.128 gathers FOUR source rows per chunk:
// lane-group g = lane>>3 owns edge g; each lane loads 16B (8 halves) of its
// group's source row (8 lanes x 16B = full 128B row). Per 4-edge chunk:
// 2 edge LDG + 1 gather LDG = 3 LDG (vs 6 before). Partial sums (8 floats
// per lane over its 16-col slice) combined at row end via shfl_xor(8,16);
// lanes 0-7 pack fp16 and store the row with one STG.128.
// ---------------------------------------------------------------------------
__global__ void __launch_bounds__(256, 6)
k_gather(const __half2* __restrict__ ego_in) {
    int tid  = threadIdx.x;
    int warp = tid >> 5, lane = tid & 31;
    int r0 = (blockIdx.x * 8 + warp) * 4;
    if (r0 >= NTOT) return;

    int  g8   = lane & 7;                 // 16B slot within a row
    bool p_hi = (lane & 16) != 0;         // edge pair select (A vs B)
    bool p_od = (lane & 8)  != 0;         // edge within pair (.x/.y vs .z/.w)
    const char* egoBase = reinterpret_cast<const char*>(ego_in) + g8 * 16;

#pragma unroll
    for (int r = 0; r < 4; r++) {
        int row = r0 + r;
        if (row >= NTOT) break;
        float a0=0.f,a1=0.f,a2=0.f,a3=0.f,a4=0.f,a5=0.f,a6=0.f,a7=0.f;
        int n4 = (g_cnt[row] + 3) & ~3;
        int s  = g_start[row];
        const uint4* ep = reinterpret_cast<const uint4*>(&g_edges[(size_t)s * 2]);

        for (int base = 0; base < n4; base += 4) {
            uint4 A = ep[base >> 1];          // edges 0,1: {c0,v0,c1,v1}
            uint4 B = ep[(base >> 1) + 1];    // edges 2,3
            unsigned cc = p_od ? (p_hi ? B.z : A.z) : (p_hi ? B.x : A.x);
            unsigned vv = p_od ? (p_hi ? B.w : A.w) : (p_hi ? B.y : A.y);
            float v = __uint_as_float(vv);
            uint4 x = *reinterpret_cast<const uint4*>(egoBase + (size_t)cc * 128);
            float2 f0 = __half22float2(*reinterpret_cast<const __half2*>(&x.x));
            float2 f1 = __half22float2(*reinterpret_cast<const __half2*>(&x.y));
            float2 f2 = __half22float2(*reinterpret_cast<const __half2*>(&x.z));
            float2 f3 = __half22float2(*reinterpret_cast<const __half2*>(&x.w));
            a0 += v * f0.x; a1 += v * f0.y;
            a2 += v * f1.x; a3 += v * f1.y;
            a4 += v * f2.x; a5 += v * f2.y;
            a6 += v * f3.x; a7 += v * f3.y;
        }

        // combine the 4 lane-groups (lanes l, l+8, l+16, l+24 share a col slice)
        a0 += __shfl_xor_sync(0xffffffffu, a0, 8);
        a1 += __shfl_xor_sync(0xffffffffu, a1, 8);
        a2 += __shfl_xor_sync(0xffffffffu, a2, 8);
        a3 += __shfl_xor_sync(0xffffffffu, a3, 8);
        a4 += __shfl_xor_sync(0xffffffffu, a4, 8);
        a5 += __shfl_xor_sync(0xffffffffu, a5, 8);
        a6 += __shfl_xor_sync(0xffffffffu, a6, 8);
        a7 += __shfl_xor_sync(0xffffffffu, a7, 8);
        a0 += __shfl_xor_sync(0xffffffffu, a0, 16);
        a1 += __shfl_xor_sync(0xffffffffu, a1, 16);
        a2 += __shfl_xor_sync(0xffffffffu, a2, 16);
        a3 += __shfl_xor_sync(0xffffffffu, a3, 16);
        a4 += __shfl_xor_sync(0xffffffffu, a4, 16);
        a5 += __shfl_xor_sync(0xffffffffu, a5, 16);
        a6 += __shfl_xor_sync(0xffffffffu, a6, 16);
        a7 += __shfl_xor_sync(0xffffffffu, a7, 16);

        if (lane < 8) {
            __align__(16) __half2 ov[4];
            ov[0] = __floats2half2_rn(a0, a1);
            ov[1] = __floats2half2_rn(a2, a3);
            ov[2] = __floats2half2_rn(a4, a5);
            ov[3] = __floats2half2_rn(a6, a7);
            *reinterpret_cast<uint4*>(
                reinterpret_cast<char*>(g_side16) + (size_t)row * 128 + g8 * 16)
                = *reinterpret_cast<const uint4*>(ov);
        }
    }
}

// ---------------------------------------------------------------------------
// dense via tensor cores: mma.sync.m16n8k16 (fp16 in, fp32 accum).
// Block = 8 warps x 16 rows = 128 rows. A frags from global fp16 side.
// B = W^T in smem fp16 [64][72]. Bias in accum init. Epilogue: leaky_relu,
// fp16 ego store, row norm via 2x shfl_xor in 4-lane group.
// ---------------------------------------------------------------------------
__global__ void __launch_bounds__(256, 4)
k_dense(__half2* __restrict__ ego_out, float* __restrict__ inv_out,
        const float* __restrict__ W, const float* __restrict__ b) {
    __shared__ __half Wt[64][72];   // Wt[n][k] = W[k][n]

    int tid = threadIdx.x;
    for (int i = tid; i < EMB * EMB; i += 256) {
        int k = i >> 6, n = i & 63;
        Wt[n][k] = __float2half(W[i]);
    }
    __syncthreads();

    int t = tid & 31, w = tid >> 5;
    int g = t >> 2, q = t & 3;
    int r0 = blockIdx.x * 128 + w * 16 + g;

    const unsigned* S0 = reinterpret_cast<const unsigned*>(g_side16) + (size_t)r0 * 32;
    const unsigned* S1 = S0 + 8 * 32;

    float c[8][4];
#pragma unroll
    for (int nn = 0; nn < 8; nn++) {
        float2 bb = *reinterpret_cast<const float2*>(&b[nn * 8 + 2 * q]);
        c[nn][0] = bb.x; c[nn][1] = bb.y; c[nn][2] = bb.x; c[nn][3] = bb.y;
    }

#pragma unroll
    for (int kk = 0; kk < 4; kk++) {
        unsigned a0 = S0[kk * 8 + q];
        unsigned a1 = S1[kk * 8 + q];
        unsigned a2 = S0[kk * 8 + q + 4];
        unsigned a3 = S1[kk * 8 + q + 4];
#pragma unroll
        for (int nn = 0; nn < 8; nn++) {
            int n = nn * 8 + g;
            unsigned b0 = *reinterpret_cast<const unsigned*>(&Wt[n][kk * 16 + 2 * q]);
            unsigned b1 = *reinterpret_cast<const unsigned*>(&Wt[n][kk * 16 + 2 * q + 8]);
            asm volatile(
                "mma.sync.aligned.m16n8k16.row.col.f32.f16.f16.f32 "
                "{%0,%1,%2,%3}, {%4,%5,%6,%7}, {%8,%9}, {%0,%1,%2,%3};"
                : "+f"(c[nn][0]), "+f"(c[nn][1]), "+f"(c[nn][2]), "+f"(c[nn][3])
                : "r"(a0), "r"(a1), "r"(a2), "r"(a3), "r"(b0), "r"(b1));
        }
    }

    float ssl = 0.f, ssh = 0.f;
#pragma unroll
    for (int nn = 0; nn < 8; nn++) {
        float e0 = c[nn][0] > 0.f ? c[nn][0] : 0.2f * c[nn][0];
        float e1 = c[nn][1] > 0.f ? c[nn][1] : 0.2f * c[nn][1];
        float e2 = c[nn][2] > 0.f ? c[nn][2] : 0.2f * c[nn][2];
        float e3 = c[nn][3] > 0.f ? c[nn][3] : 0.2f * c[nn][3];
        ego_out[(size_t)r0 * 32       + nn * 4 + q] = __floats2half2_rn(e0, e1);
        ego_out[(size_t)(r0 + 8) * 32 + nn * 4 + q] = __floats2half2_rn(e2, e3);
        ssl += e0 * e0 + e1 * e1;
        ssh += e2 * e2 + e3 * e3;
    }
    ssl += __shfl_xor_sync(0xffffffffu, ssl, 1);
    ssl += __shfl_xor_sync(0xffffffffu, ssl, 2);
    ssh += __shfl_xor_sync(0xffffffffu, ssh, 1);
    ssh += __shfl_xor_sync(0xffffffffu, ssh, 2);
    if (q == 0) {
        inv_out[r0]     = 1.f / fmaxf(sqrtf(ssl), 1e-12f);
        inv_out[r0 + 8] = 1.f / fmaxf(sqrtf(ssh), 1e-12f);
    }
}

// ---------------------------------------------------------------------------
// final launch: out[u] = ue[u] + sum_l ego_l[u] * inv_l[u].
// Egos: B = layer1, C = layer2, A = layer3. Re-zeroes g_cnt / g_ctr.
// ---------------------------------------------------------------------------
__global__ void k_out(const int* __restrict__ users, const float* __restrict__ ue,
                      float* __restrict__ out) {
    int i = blockIdx.x * blockDim.x + threadIdx.x;
    if (i < NTOT) g_cnt[i] = 0;
    if (i == 0)   g_ctr = 0;
    if (i >= BATCH * EMB) return;
    int row = i >> 6, col = i & 63;
    int u = users[row];
    const __half* e1 = reinterpret_cast<const __half*>(g_egoB);
    const __half* e2 = reinterpret_cast<const __half*>(g_egoC);
    const __half* e3 = reinterpret_cast<const __half*>(g_egoA);
    size_t idx = (size_t)u * EMB + col;
    out[i] = ue[idx]
           + __half2float(e1[idx]) * g_inv[0][u]
           + __half2float(e2[idx]) * g_inv[1][u]
           + __half2float(e3[idx]) * g_inv[2][u];
}

// ---------------------------------------------------------------------------
extern "C" void kernel_launch(void* const* d_in, const int* in_sizes, int n_in,
                              void* d_out, int out_size) {
    const int*   users = (const int*)d_in[0];
    const int*   rows  = (const int*)d_in[1];
    const int*   cols  = (const int*)d_in[2];
    const float* vals  = (const float*)d_in[3];
    const float* ue    = (const float*)d_in[4];
    const float* ie    = (const float*)d_in[5];
    const float* Wl[3] = {(const float*)d_in[6], (const float*)d_in[8],  (const float*)d_in[10]};
    const float* Bl[3] = {(const float*)d_in[7], (const float*)d_in[9],  (const float*)d_in[11]};

    __half2 *egoA, *egoB, *egoC;
    float* invBase;
    cudaGetSymbolAddress((void**)&egoA, g_egoA);
    cudaGetSymbolAddress((void**)&egoB, g_egoB);
    cudaGetSymbolAddress((void**)&egoC, g_egoC);
    cudaGetSymbolAddress((void**)&invBase, g_inv);

    // 0: init + hist; 1: alloc (+pad edges to x4); 2: fill
    k_init_hist<<<(NNZ + 255) / 256, 256>>>((const float4*)ue, (const float4*)ie, rows);
    k_alloc<<<(NTOT + 255) / 256, 256>>>();
    k_fill<<<(NNZ + 255) / 256, 256>>>(rows, cols, vals);

    // layers: gather (launch #3 profiled) + tensor-core dense, x3
    const int GG = (NTOT + 31) / 32;     // gather: 32 rows/block
    const int GD = NTOTP / 128;          // dense: 128 rows/block
    k_gather<<<GG, 256>>>(egoA);
    k_dense <<<GD, 256>>>(egoB, invBase + 0 * NTOTP, Wl[0], Bl[0]);
    k_gather<<<GG, 256>>>(egoB);
    k_dense <<<GD, 256>>>(egoC, invBase + 1 * NTOTP, Wl[1], Bl[1]);
    k_gather<<<GG, 256>>>(egoC);
    k_dense <<<GD, 256>>>(egoA, invBase + 2 * NTOTP, Wl[2], Bl[2]);

    // output gather + counter re-zero
    k_out<<<(BATCH * EMB + 255) / 256, 256>>>(users, ue, (float*)d_out);
}

// round 17
// speedup vs baseline: 1.0821x; 1.0821x over previous
#include <cuda_runtime.h>
#include <cuda_fp16.h>
#include <cstdint>

#define N_USER 50000
#define N_ITEM 100000
#define NTOT   150000
#define NTOTP  150016            // padded to multiple of 128 (dense block rows)
#define NNZ    3000000
#define EMB    64
#define BATCH  4096
#define NPAD   (NNZ + NTOT * 4 + 8)   // edges + worst-case per-row pad (x4)

// ---------------- device scratch (no allocation allowed) --------------------
__device__ __align__(16) __half2 g_egoA[(size_t)NTOTP * 32];  // init ego, then layer-3 ego
__device__ __align__(16) __half2 g_egoB[(size_t)NTOTP * 32];  // layer-1 ego
__device__ __align__(16) __half2 g_egoC[(size_t)NTOTP * 32];  // layer-2 ego
__device__ __align__(16) __half2 g_side16[(size_t)NTOTP * 32];// fp16 side scratch
__device__ float g_inv[3][NTOTP];                             // per-layer inv norms
__device__ __align__(16) unsigned g_edges[(size_t)NPAD * 2];  // {col, valbits} pairs
__device__ int g_cnt[NTOT];     // zeroed by k_out at end of every call
__device__ int g_start[NTOT];
__device__ int g_cur[NTOT];
__device__ int g_ctr;           // zeroed by k_out at end of every call

// ---------------------------------------------------------------------------
// launch 0: fused init + histogram. g_cnt/g_ctr zero at entry.
// ---------------------------------------------------------------------------
__global__ void k_init_hist(const float4* __restrict__ ue, const float4* __restrict__ ie,
                            const int* __restrict__ rows) {
    int i = blockIdx.x * blockDim.x + threadIdx.x;   // grid covers NNZ (3M)
    if (i < NTOT * 16) {
        float4 v = (i < N_USER * 16) ? ue[i] : ie[i - N_USER * 16];
        g_egoA[2 * i]     = __floats2half2_rn(v.x, v.y);
        g_egoA[2 * i + 1] = __floats2half2_rn(v.z, v.w);
    }
    if (i < NNZ) atomicAdd(&g_cnt[rows[i]], 1);
}

// launch 1: atomic segment allocation (x4-padded); writes {0,0} pad edges.
__global__ void k_alloc() {
    int r = blockIdx.x * blockDim.x + threadIdx.x;
    if (r >= NTOT) return;
    int cnt = g_cnt[r];
    int c4  = (cnt + 3) & ~3;
    int s = atomicAdd(&g_ctr, c4);
    g_start[r] = s;
    g_cur[r]   = s;
    uint2* ez = reinterpret_cast<uint2*>(g_edges);
    for (int j = cnt; j < c4; j++) ez[s + j] = make_uint2(0u, 0u);
}

// launch 2: permute edges into row-grouped segments
__global__ void k_fill(const int* __restrict__ rows, const int* __restrict__ cols,
                       const float* __restrict__ vals) {
    int i = blockIdx.x * blockDim.x + threadIdx.x;
    if (i >= NNZ) return;
    int r = rows[i];
    int p = atomicAdd(&g_cur[r], 1);
    uint2* ez = reinterpret_cast<uint2*>(g_edges);
    ez[p] = make_uint2((unsigned)cols[i], __float_as_uint(vals[i]));
}

// ---------------------------------------------------------------------------
// gather: minimal instruction stream. Lane-group g = lane>>3 owns edge g of
// each 4-edge chunk; the lane LOADS ITS OWN edge record (LDG.64, 4 distinct
// 8B addrs = 1 wavefront) — no broadcast+SEL routing. One LDG.128 then
// fetches 16B of the group's source row (8 lanes x 16B = full 128B row, so
// the single instruction gathers 4 rows). Per 4-edge chunk: 2 LDG + 8 cvt +
// 8 FFMA + ~3 overhead = ~21 instrs (R14: 34, R16: 35). Row epilogue:
// shfl_xor(8,16) tree in fp32, lanes 0-7 pack fp16, one STG.128.
// ---------------------------------------------------------------------------
__global__ void __launch_bounds__(256, 6)
k_gather(const __half2* __restrict__ ego_in) {
    int tid  = threadIdx.x;
    int warp = tid >> 5, lane = tid & 31;
    int r0 = (blockIdx.x * 8 + warp) * 4;
    if (r0 >= NTOT) return;

    int g8 = lane & 7;                    // 16B slot within a row
    int eg = lane >> 3;                   // edge-group 0..3
    const char* egoBase = reinterpret_cast<const char*>(ego_in) + g8 * 16;

#pragma unroll
    for (int r = 0; r < 4; r++) {
        int row = r0 + r;
        if (row >= NTOT) break;
        float a0=0.f,a1=0.f,a2=0.f,a3=0.f,a4=0.f,a5=0.f,a6=0.f,a7=0.f;
        int n4 = (g_cnt[row] + 3) & ~3;
        const uint2* ep = reinterpret_cast<const uint2*>(
                              &g_edges[(size_t)g_start[row] * 2]) + eg;

        for (int base = 0; base < n4; base += 4) {
            uint2 e = ep[base];                           // this lane's edge
            uint4 x = *reinterpret_cast<const uint4*>(egoBase + (size_t)e.x * 128);
            float v = __uint_as_float(e.y);
            float2 f0 = __half22float2(*reinterpret_cast<const __half2*>(&x.x));
            float2 f1 = __half22float2(*reinterpret_cast<const __half2*>(&x.y));
            float2 f2 = __half22float2(*reinterpret_cast<const __half2*>(&x.z));
            float2 f3 = __half22float2(*reinterpret_cast<const __half2*>(&x.w));
            a0 += v * f0.x; a1 += v * f0.y;
            a2 += v * f1.x; a3 += v * f1.y;
            a4 += v * f2.x; a5 += v * f2.y;
            a6 += v * f3.x; a7 += v * f3.y;
        }

        // combine the 4 edge-groups (lanes l, l+8, l+16, l+24 share a slice)
        a0 += __shfl_xor_sync(0xffffffffu, a0, 8);
        a1 += __shfl_xor_sync(0xffffffffu, a1, 8);
        a2 += __shfl_xor_sync(0xffffffffu, a2, 8);
        a3 += __shfl_xor_sync(0xffffffffu, a3, 8);
        a4 += __shfl_xor_sync(0xffffffffu, a4, 8);
        a5 += __shfl_xor_sync(0xffffffffu, a5, 8);
        a6 += __shfl_xor_sync(0xffffffffu, a6, 8);
        a7 += __shfl_xor_sync(0xffffffffu, a7, 8);
        a0 += __shfl_xor_sync(0xffffffffu, a0, 16);
        a1 += __shfl_xor_sync(0xffffffffu, a1, 16);
        a2 += __shfl_xor_sync(0xffffffffu, a2, 16);
        a3 += __shfl_xor_sync(0xffffffffu, a3, 16);
        a4 += __shfl_xor_sync(0xffffffffu, a4, 16);
        a5 += __shfl_xor_sync(0xffffffffu, a5, 16);
        a6 += __shfl_xor_sync(0xffffffffu, a6, 16);
        a7 += __shfl_xor_sync(0xffffffffu, a7, 16);

        if (lane < 8) {
            __align__(16) __half2 ov[4];
            ov[0] = __floats2half2_rn(a0, a1);
            ov[1] = __floats2half2_rn(a2, a3);
            ov[2] = __floats2half2_rn(a4, a5);
            ov[3] = __floats2half2_rn(a6, a7);
            *reinterpret_cast<uint4*>(
                reinterpret_cast<char*>(g_side16) + (size_t)row * 128 + g8 * 16)
                = *reinterpret_cast<const uint4*>(ov);
        }
    }
}

// ---------------------------------------------------------------------------
// dense via tensor cores: mma.sync.m16n8k16 (fp16 in, fp32 accum).
// Block = 8 warps x 16 rows = 128 rows. A frags from global fp16 side.
// B = W^T in smem fp16 [64][72]. Bias in accum init. Epilogue: leaky_relu,
// fp16 ego store, row norm via 2x shfl_xor in 4-lane group.
// ---------------------------------------------------------------------------
__global__ void __launch_bounds__(256, 4)
k_dense(__half2* __restrict__ ego_out, float* __restrict__ inv_out,
        const float* __restrict__ W, const float* __restrict__ b) {
    __shared__ __half Wt[64][72];   // Wt[n][k] = W[k][n]

    int tid = threadIdx.x;
    for (int i = tid; i < EMB * EMB; i += 256) {
        int k = i >> 6, n = i & 63;
        Wt[n][k] = __float2half(W[i]);
    }
    __syncthreads();

    int t = tid & 31, w = tid >> 5;
    int g = t >> 2, q = t & 3;
    int r0 = blockIdx.x * 128 + w * 16 + g;

    const unsigned* S0 = reinterpret_cast<const unsigned*>(g_side16) + (size_t)r0 * 32;
    const unsigned* S1 = S0 + 8 * 32;

    float c[8][4];
#pragma unroll
    for (int nn = 0; nn < 8; nn++) {
        float2 bb = *reinterpret_cast<const float2*>(&b[nn * 8 + 2 * q]);
        c[nn][0] = bb.x; c[nn][1] = bb.y; c[nn][2] = bb.x; c[nn][3] = bb.y;
    }

#pragma unroll
    for (int kk = 0; kk < 4; kk++) {
        unsigned a0 = S0[kk * 8 + q];
        unsigned a1 = S1[kk * 8 + q];
        unsigned a2 = S0[kk * 8 + q + 4];
        unsigned a3 = S1[kk * 8 + q + 4];
#pragma unroll
        for (int nn = 0; nn < 8; nn++) {
            int n = nn * 8 + g;
            unsigned b0 = *reinterpret_cast<const unsigned*>(&Wt[n][kk * 16 + 2 * q]);
            unsigned b1 = *reinterpret_cast<const unsigned*>(&Wt[n][kk * 16 + 2 * q + 8]);
            asm volatile(
                "mma.sync.aligned.m16n8k16.row.col.f32.f16.f16.f32 "
                "{%0,%1,%2,%3}, {%4,%5,%6,%7}, {%8,%9}, {%0,%1,%2,%3};"
                : "+f"(c[nn][0]), "+f"(c[nn][1]), "+f"(c[nn][2]), "+f"(c[nn][3])
                : "r"(a0), "r"(a1), "r"(a2), "r"(a3), "r"(b0), "r"(b1));
        }
    }

    float ssl = 0.f, ssh = 0.f;
#pragma unroll
    for (int nn = 0; nn < 8; nn++) {
        float e0 = c[nn][0] > 0.f ? c[nn][0] : 0.2f * c[nn][0];
        float e1 = c[nn][1] > 0.f ? c[nn][1] : 0.2f * c[nn][1];
        float e2 = c[nn][2] > 0.f ? c[nn][2] : 0.2f * c[nn][2];
        float e3 = c[nn][3] > 0.f ? c[nn][3] : 0.2f * c[nn][3];
        ego_out[(size_t)r0 * 32       + nn * 4 + q] = __floats2half2_rn(e0, e1);
        ego_out[(size_t)(r0 + 8) * 32 + nn * 4 + q] = __floats2half2_rn(e2, e3);
        ssl += e0 * e0 + e1 * e1;
        ssh += e2 * e2 + e3 * e3;
    }
    ssl += __shfl_xor_sync(0xffffffffu, ssl, 1);
    ssl += __shfl_xor_sync(0xffffffffu, ssl, 2);
    ssh += __shfl_xor_sync(0xffffffffu, ssh, 1);
    ssh += __shfl_xor_sync(0xffffffffu, ssh, 2);
    if (q == 0) {
        inv_out[r0]     = 1.f / fmaxf(sqrtf(ssl), 1e-12f);
        inv_out[r0 + 8] = 1.f / fmaxf(sqrtf(ssh), 1e-12f);
    }
}

// ---------------------------------------------------------------------------
// final launch: out[u] = ue[u] + sum_l ego_l[u] * inv_l[u].
// Egos: B = layer1, C = layer2, A = layer3. Re-zeroes g_cnt / g_ctr.
// ---------------------------------------------------------------------------
__global__ void k_out(const int* __restrict__ users, const float* __restrict__ ue,
                      float* __restrict__ out) {
    int i = blockIdx.x * blockDim.x + threadIdx.x;
    if (i < NTOT) g_cnt[i] = 0;
    if (i == 0)   g_ctr = 0;
    if (i >= BATCH * EMB) return;
    int row = i >> 6, col = i & 63;
    int u = users[row];
    const __half* e1 = reinterpret_cast<const __half*>(g_egoB);
    const __half* e2 = reinterpret_cast<const __half*>(g_egoC);
    const __half* e3 = reinterpret_cast<const __half*>(g_egoA);
    size_t idx = (size_t)u * EMB + col;
    out[i] = ue[idx]
           + __half2float(e1[idx]) * g_inv[0][u]
           + __half2float(e2[idx]) * g_inv[1][u]
           + __half2float(e3[idx]) * g_inv[2][u];
}

// ---------------------------------------------------------------------------
extern "C" void kernel_launch(void* const* d_in, const int* in_sizes, int n_in,
                              void* d_out, int out_size) {
    const int*   users = (const int*)d_in[0];
    const int*   rows  = (const int*)d_in[1];
    const int*   cols  = (const int*)d_in[2];
    const float* vals  = (const float*)d_in[3];
    const float* ue    = (const float*)d_in[4];
    const float* ie    = (const float*)d_in[5];
    const float* Wl[3] = {(const float*)d_in[6], (const float*)d_in[8],  (const float*)d_in[10]};
    const float* Bl[3] = {(const float*)d_in[7], (const float*)d_in[9],  (const float*)d_in[11]};

    __half2 *egoA, *egoB, *egoC;
    float* invBase;
    cudaGetSymbolAddress((void**)&egoA, g_egoA);
    cudaGetSymbolAddress((void**)&egoB, g_egoB);
    cudaGetSymbolAddress((void**)&egoC, g_egoC);
    cudaGetSymbolAddress((void**)&invBase, g_inv);

    // 0: init + hist; 1: alloc (+pad edges to x4); 2: fill
    k_init_hist<<<(NNZ + 255) / 256, 256>>>((const float4*)ue, (const float4*)ie, rows);
    k_alloc<<<(NTOT + 255) / 256, 256>>>();
    k_fill<<<(NNZ + 255) / 256, 256>>>(rows, cols, vals);

    // layers: gather (launch #3 profiled) + tensor-core dense, x3
    const int GG = (NTOT + 31) / 32;     // gather: 32 rows/block
    const int GD = NTOTP / 128;          // dense: 128 rows/block
    k_gather<<<GG, 256>>>(egoA);
    k_dense <<<GD, 256>>>(egoB, invBase + 0 * NTOTP, Wl[0], Bl[0]);
    k_gather<<<GG, 256>>>(egoB);
    k_dense <<<GD, 256>>>(egoC, invBase + 1 * NTOTP, Wl[1], Bl[1]);
    k_gather<<<GG, 256>>>(egoC);
    k_dense <<<GD, 256>>>(egoA, invBase + 2 * NTOTP, Wl[2], Bl[2]);

    // output gather + counter re-zero
    k_out<<<(BATCH * EMB + 255) / 256, 256>>>(users, ue, (float*)d_out);
}